// round 2
// baseline (speedup 1.0000x reference)
#include <cuda_runtime.h>
#include <cstdint>
#include <cstddef>

#define NN 50000
#define DD 256
#define EE 1000000
#define ET (EE + NN)   // edges including self-loops

// ---- device scratch (no malloc allowed) ----
__device__ float g_Y[2][NN][128];      // [matrix m: 0=h,1=t][node][ src-proj(64) | dst-proj(64) ]
__device__ float g_a[2][NN][4];        // [m][node][ a_src_h0, a_src_h1, a_dst_h0, a_dst_h1 ]
__device__ float g_eal[2][ET][2];      // exp(alpha) per direction/edge/head
__device__ float g_den[2][NN][2];      // softmax denominators
__device__ int   g_is64;               // edge_index dtype flag

__device__ __forceinline__ float elu1(float x) {
    return x > 0.f ? x : expm1f(x);
}

// Detect whether edge_index is int64 (odd 32-bit words all zero since values < 50000)
__global__ void detect_kernel(const int* __restrict__ ei32) {
    if (threadIdx.x == 0 && blockIdx.x == 0) {
        int z = ei32[1] | ei32[3] | ei32[5] | ei32[7] | ei32[9] | ei32[11] | ei32[13];
        g_is64 = (z == 0) ? 1 : 0;
    }
}

// Y[m] = elu(X_m) @ [W_src | W_dst], M=50000, N=128, K=256
__global__ __launch_bounds__(256) void gemm_kernel(
    const float* __restrict__ hx, const float* __restrict__ txp,
    const float* __restrict__ Wsrc, const float* __restrict__ Wdst)
{
    const int m = blockIdx.y;
    const float* __restrict__ X = (m == 0) ? hx : txp;
    __shared__ float  As[32][130];   // [k][row], padded
    __shared__ float4 Bs[32][32];    // [k][j4]  (128 cols as 32 float4)
    const int tid = threadIdx.x;
    const int tcx = tid & 15, tcy = tid >> 4;
    const int row0 = blockIdx.x * 128;

    float acc[8][8];
    #pragma unroll
    for (int i = 0; i < 8; i++)
        #pragma unroll
        for (int j = 0; j < 8; j++) acc[i][j] = 0.f;

    for (int k0 = 0; k0 < DD; k0 += 32) {
        // load A tile (transposed into smem) with ELU applied
        #pragma unroll
        for (int it = 0; it < 4; it++) {
            int l = tid + 256 * it;
            int r = l >> 3, k4 = l & 7;
            int grow = row0 + r;
            float4 v = make_float4(0.f, 0.f, 0.f, 0.f);
            if (grow < NN) v = *(const float4*)&X[(size_t)grow * DD + k0 + k4 * 4];
            As[k4*4+0][r] = elu1(v.x);
            As[k4*4+1][r] = elu1(v.y);
            As[k4*4+2][r] = elu1(v.z);
            As[k4*4+3][r] = elu1(v.w);
        }
        // load B tile: cols 0..63 from W_src, 64..127 from W_dst
        #pragma unroll
        for (int it = 0; it < 4; it++) {
            int l = tid + 256 * it;
            int kk = l >> 5, j4 = l & 31;
            float4 v;
            if (j4 < 16) v = *(const float4*)&Wsrc[(size_t)(k0 + kk) * 64 + j4 * 4];
            else         v = *(const float4*)&Wdst[(size_t)(k0 + kk) * 64 + (j4 - 16) * 4];
            Bs[kk][j4] = v;
        }
        __syncthreads();
        #pragma unroll
        for (int kk = 0; kk < 32; kk++) {
            float a[8], b[8];
            #pragma unroll
            for (int i = 0; i < 8; i++) a[i] = As[kk][tcy * 8 + i];
            float4 b0 = Bs[kk][tcx * 2], b1 = Bs[kk][tcx * 2 + 1];
            b[0]=b0.x; b[1]=b0.y; b[2]=b0.z; b[3]=b0.w;
            b[4]=b1.x; b[5]=b1.y; b[6]=b1.z; b[7]=b1.w;
            #pragma unroll
            for (int i = 0; i < 8; i++)
                #pragma unroll
                for (int j = 0; j < 8; j++)
                    acc[i][j] = fmaf(a[i], b[j], acc[i][j]);
        }
        __syncthreads();
    }
    #pragma unroll
    for (int i = 0; i < 8; i++) {
        int grow = row0 + tcy * 8 + i;
        if (grow < NN) {
            float4* dst = (float4*)&g_Y[m][grow][0];
            dst[tcx*2]   = make_float4(acc[i][0], acc[i][1], acc[i][2], acc[i][3]);
            dst[tcx*2+1] = make_float4(acc[i][4], acc[i][5], acc[i][6], acc[i][7]);
        }
    }
}

// a_s / a_d per node/head: dot of 32 channels with attention vector
__global__ void acomp_kernel(const float* __restrict__ att_src,
                             const float* __restrict__ att_dst) {
    int idx = blockIdx.x * blockDim.x + threadIdx.x;
    if (idx >= 2 * NN * 4) return;
    int m = idx >= NN * 4;
    int r = idx - m * NN * 4;
    int n = r >> 2;
    int q = r & 3;               // 0,1: src h0/h1 ; 2,3: dst h0/h1
    int kind = q >> 1, h = q & 1;
    const float4* y4 = (const float4*)&g_Y[m][n][kind * 64 + h * 32];
    const float4* a4 = (const float4*)(kind ? att_dst : att_src) + h * 8;
    float sacc = 0.f;
    #pragma unroll
    for (int i = 0; i < 8; i++) {
        float4 yv = y4[i], av = a4[i];
        sacc += yv.x * av.x + yv.y * av.y + yv.z * av.z + yv.w * av.w;
    }
    g_a[m][n][q] = sacc;
}

// out := bias (both halves), denom := 0
__global__ void init_kernel(const float* __restrict__ bias, float* __restrict__ out) {
    int i = blockIdx.x * blockDim.x + threadIdx.x;
    if (i < 2 * NN * 16) {
        ((float4*)out)[i] = ((const float4*)bias)[i & 15];
    }
    if (i < NN) {  // 2*NN*2 floats = NN float4
        ((float4*)g_den)[i] = make_float4(0.f, 0.f, 0.f, 0.f);
    }
}

__device__ __forceinline__ void decode_edge(const void* eiv, int e, int dir,
                                            int& s, int& d) {
    if (e < EE) {
        int a, b;
        if (g_is64) {
            const long long* ei = (const long long*)eiv;
            a = (int)__ldg(&ei[e]); b = (int)__ldg(&ei[EE + e]);
        } else {
            const int* ei = (const int*)eiv;
            a = __ldg(&ei[e]); b = __ldg(&ei[EE + e]);
        }
        s = (dir == 0) ? a : b;
        d = (dir == 0) ? b : a;
    } else {
        s = d = e - EE;   // self-loop
    }
}

// per-edge: alpha = leaky_relu(a_s[s]+a_d[d]); store exp; accumulate denom
__global__ __launch_bounds__(256) void esoft_kernel(const void* __restrict__ eiv) {
    const int dir = blockIdx.y;           // 0: h->t (t_rep), 1: t->h (h_rep)
    const int e = blockIdx.x * blockDim.x + threadIdx.x;
    if (e >= ET) return;
    int s, d;
    decode_edge(eiv, e, dir, s, d);
    const int ms = dir, md = 1 - dir;     // matrix index of src / dst features
    #pragma unroll
    for (int h = 0; h < 2; h++) {
        float al = g_a[ms][s][h] + g_a[md][d][2 + h];
        al = al > 0.f ? al : 0.2f * al;
        float ea = expf(al);
        g_eal[dir][e][h] = ea;
        atomicAdd(&g_den[dir][d][h], ea);
    }
}

// 16 threads per edge, one float4 vector-red each (64 floats/edge)
__global__ __launch_bounds__(256) void aggr_kernel(const void* __restrict__ eiv,
                                                   float* __restrict__ out) {
    const int dir = blockIdx.y;
    long long gt = (long long)blockIdx.x * 256 + threadIdx.x;
    int e  = (int)(gt >> 4);
    int c4 = (int)(gt & 15);
    if (e >= ET) return;
    int s, d;
    decode_edge(eiv, e, dir, s, d);
    int h = c4 >> 3;
    float w = g_eal[dir][e][h] / (g_den[dir][d][h] + 1e-16f);
    float4 v = *(const float4*)&g_Y[dir][s][c4 * 4];   // src-proj = first 64 cols
    // dir0 writes t_rep (second half of out), dir1 writes h_rep (first half)
    float* dp = out + ((dir == 0) ? (size_t)NN * 64 : (size_t)0)
                    + (size_t)d * 64 + c4 * 4;
    asm volatile("red.global.add.v4.f32 [%0], {%1,%2,%3,%4};"
                 :: "l"(dp), "f"(w * v.x), "f"(w * v.y), "f"(w * v.z), "f"(w * v.w)
                 : "memory");
}

extern "C" void kernel_launch(void* const* d_in, const int* in_sizes, int n_in,
                              void* d_out, int out_size) {
    const float* hx      = (const float*)d_in[0];
    const float* txp     = (const float*)d_in[1];
    const void*  ei      = d_in[2];               // int32 or int64, auto-detected
    const float* Wsrc    = (const float*)d_in[3];
    const float* Wdst    = (const float*)d_in[4];
    const float* att_src = (const float*)d_in[5];
    const float* att_dst = (const float*)d_in[6];
    const float* bias    = (const float*)d_in[7];
    float* out = (float*)d_out;

    detect_kernel<<<1, 32>>>((const int*)ei);
    gemm_kernel<<<dim3((NN + 127) / 128, 2), 256>>>(hx, txp, Wsrc, Wdst);
    acomp_kernel<<<(2 * NN * 4 + 255) / 256, 256>>>(att_src, att_dst);
    init_kernel<<<(2 * NN * 16 + 255) / 256, 256>>>(bias, out);
    esoft_kernel<<<dim3((ET + 255) / 256, 2), 256>>>(ei);
    {
        long long total = (long long)ET * 16;
        int blocks = (int)((total + 255) / 256);
        aggr_kernel<<<dim3(blocks, 2), 256>>>(ei, out);
    }
}